// round 15
// baseline (speedup 1.0000x reference)
#include <cuda_runtime.h>
#include <cuda_fp16.h>
#include <math.h>
#include <stdint.h>

// ---------------------------------------------------------------------------
// SpikeAttention (linear attention, ELU+1 feature map)
//   B=4, N=4096, DIM=1024, HEADS=16, HEAD_DIM=64
// Round 15: GBN=128 tiles for both GEMMs (wave-tail reduction: gemm_o
// 3.46->6.9 waves, qkv 10.4->20.8), tail folded into conv. GEMM core is at
// the fp32-accum HMMA peak (~290 TF/s); only tails/launches left to mine.
// ---------------------------------------------------------------------------

#define BDIM  4
#define NSEQ  4096
#define DIM   1024
#define HEADS 16
#define HD    64
#define MTOT  (BDIM * NSEQ)          // 16384

__device__ float g_KV[BDIM * HEADS * HD * HD];
__device__ float g_Ksum[BDIM * HEADS * HD];

__device__ __align__(16) __half g_Q[(size_t)MTOT * DIM];
__device__ __align__(16) __half g_K[(size_t)MTOT * DIM];
__device__ __align__(16) __half g_V[(size_t)MTOT * DIM];
__device__ __align__(16) __half g_xh[(size_t)MTOT * DIM];
__device__ __align__(16) __half g_ah[(size_t)MTOT * DIM];
__device__ __align__(16) __half g_wh[4][DIM * DIM];

// ---------------------------------------------------------------------------
// fused conversion kernel: x->fp16, W*->fp16, zero KV/Ksum, out tail. 1 launch
// ---------------------------------------------------------------------------
#define CV_XBLK (MTOT * DIM / 4 / 256)       // 16384
#define CV_WBLK 4096
#define CV_ZBLK ((BDIM * HEADS * HD * HD + 255) / 256 + 1)  // 1025
__global__ __launch_bounds__(256)
void conv_kernel(const float* __restrict__ x,
                 const float* __restrict__ Wq, const float* __restrict__ Wk,
                 const float* __restrict__ Wv, const float* __restrict__ Wo,
                 const float* __restrict__ stdp,
                 float* __restrict__ out, int extra)
{
    const int bid = blockIdx.x;
    if (bid < CV_XBLK) {
        const int i = bid * 256 + threadIdx.x;
        float4 f = ((const float4*)x)[i];
        ((__half2*)g_xh)[2 * i + 0] = __halves2half2(__float2half_rn(f.x),
                                                     __float2half_rn(f.y));
        ((__half2*)g_xh)[2 * i + 1] = __halves2half2(__float2half_rn(f.z),
                                                     __float2half_rn(f.w));
    } else if (bid < CV_XBLK + CV_WBLK) {
        const int wb = bid - CV_XBLK;
        const int mat = wb >> 10;
        const int i = (wb & 1023) * 256 + threadIdx.x;
        const float* src = (mat == 0) ? Wq : (mat == 1) ? Wk
                         : (mat == 2) ? Wv : Wo;
        float4 f = ((const float4*)src)[i];
        ((__half2*)g_wh[mat])[2 * i + 0] = __halves2half2(__float2half_rn(f.x),
                                                          __float2half_rn(f.y));
        ((__half2*)g_wh[mat])[2 * i + 1] = __halves2half2(__float2half_rn(f.z),
                                                          __float2half_rn(f.w));
    } else {
        const int i = (bid - CV_XBLK - CV_WBLK) * 256 + threadIdx.x;
        if (i < BDIM * HEADS * HD * HD) g_KV[i] = 0.f;
        if (i < BDIM * HEADS * HD)      g_Ksum[i] = 0.f;
        if (i < extra)
            out[(size_t)MTOT * DIM + i] = (i < HEADS) ? stdp[i] : 0.f;
    }
}

// ===========================================================================
// Shared PTX helpers
// ===========================================================================
__device__ __forceinline__ uint32_t smem_u32(const void* p) {
    uint32_t a;
    asm("{ .reg .u64 t; cvta.to.shared.u64 t, %1; cvt.u32.u64 %0, t; }"
        : "=r"(a) : "l"(p));
    return a;
}
__device__ __forceinline__ void cp16(uint32_t dst, const void* src) {
    asm volatile("cp.async.cg.shared.global [%0], [%1], 16;"
                 :: "r"(dst), "l"(src));
}
__device__ __forceinline__ void ldm4(uint32_t* r, uint32_t addr) {
    asm volatile("ldmatrix.sync.aligned.m8n8.x4.shared.b16 {%0,%1,%2,%3}, [%4];"
                 : "=r"(r[0]), "=r"(r[1]), "=r"(r[2]), "=r"(r[3]) : "r"(addr));
}
__device__ __forceinline__ void ldm4t(uint32_t* r, uint32_t addr) {
    asm volatile("ldmatrix.sync.aligned.m8n8.x4.trans.shared.b16 {%0,%1,%2,%3}, [%4];"
                 : "=r"(r[0]), "=r"(r[1]), "=r"(r[2]), "=r"(r[3]) : "r"(addr));
}
__device__ __forceinline__ void mma_f16(float* c, const uint32_t* a,
                                        const uint32_t* b) {
    asm volatile(
        "mma.sync.aligned.m16n8k16.row.col.f32.f16.f16.f32 "
        "{%0,%1,%2,%3}, {%4,%5,%6,%7}, {%8,%9}, {%0,%1,%2,%3};"
        : "+f"(c[0]), "+f"(c[1]), "+f"(c[2]), "+f"(c[3])
        : "r"(a[0]), "r"(a[1]), "r"(a[2]), "r"(a[3]), "r"(b[0]), "r"(b[1]));
}

// ===========================================================================
// GEMM core: 128x128 CTA tile, GBK=64, 4-stage cp.async, 512 threads,
// 16 warps (4M x 4N), each warp owns 32x32.
// ===========================================================================
#define GBM 128
#define GBN 128
#define GBK 64
#define NCHUNK (DIM / GBK)           // 16
#define RS 144
#define TILE_A (128 * RS)            // 18432
#define TILE_W (128 * RS)            // 18432
#define STAGE_B (TILE_A + TILE_W)    // 36864
#define GSTAGES 4
#define SMEMG (GSTAGES * STAGE_B)    // 147456
#define GTHREADS 512

__device__ __forceinline__
void gemm_body(const __half* __restrict__ A,
               const __half* __restrict__ W,
               const float* __restrict__ bias,
               void* __restrict__ C,
               int m0, int n0, int act, int fp16out, char* smem)
{
    const uint32_t sbase = smem_u32(smem);
    const int tid = threadIdx.x;
    const int lane = tid & 31;
    const int wid = tid >> 5;        // 0..15
    const int wm = wid & 3;          // 4 warps over M (32 rows)
    const int wn = wid >> 2;         // 4 warps over N (32 cols)

    // stage loader: 2048 x 16B granules (A:1024, W:1024), 4 per thread
    auto load_stage = [&](int ck, int slot) {
        const uint32_t sb = sbase + slot * STAGE_B;
        const int kofs = ck * GBK;
        #pragma unroll
        for (int i = 0; i < 4; i++) {
            const int id = tid + i * GTHREADS;   // 0..2047
            uint32_t dst;
            const __half* src;
            if (id < 1024) {
                const int r = id >> 3, c = id & 7;
                dst = sb + r * RS + c * 16;
                src = A + (size_t)(m0 + r) * DIM + kofs + c * 8;
            } else {
                const int id2 = id - 1024;
                const int r = id2 >> 3, c = id2 & 7;
                dst = sb + TILE_A + r * RS + c * 16;
                src = W + (size_t)(n0 + r) * DIM + kofs + c * 8;
            }
            cp16(dst, src);
        }
    };

    load_stage(0, 0);
    asm volatile("cp.async.commit_group;");
    load_stage(1, 1);
    asm volatile("cp.async.commit_group;");
    load_stage(2, 2);
    asm volatile("cp.async.commit_group;");

    float acc[2][4][4];
    #pragma unroll
    for (int mf = 0; mf < 2; mf++)
        #pragma unroll
        for (int nf = 0; nf < 4; nf++)
            #pragma unroll
            for (int e = 0; e < 4; e++) acc[mf][nf][e] = 0.f;

    const int rl = lane & 15;
    const int cb16 = (lane >> 4) << 4;

    for (int ck = 0; ck < NCHUNK; ck++) {
        asm volatile("cp.async.wait_group 2;");
        __syncthreads();
        if (ck + 3 < NCHUNK) load_stage(ck + 3, (ck + 3) & (GSTAGES - 1));
        asm volatile("cp.async.commit_group;");

        const uint32_t sb = sbase + (ck & (GSTAGES - 1)) * STAGE_B;
        #pragma unroll
        for (int k16 = 0; k16 < 4; k16++) {
            const int cb = k16 * 32 + cb16;
            uint32_t ar[2][4], bf[4][2];
            #pragma unroll
            for (int mf = 0; mf < 2; mf++) {
                const uint32_t ra = (wm * 32 + mf * 16 + rl) * RS + cb;
                ldm4(ar[mf], sb + ra);
            }
            #pragma unroll
            for (int p = 0; p < 2; p++) {
                const uint32_t rb = (wn * 32 + p * 16 + rl) * RS + cb;
                uint32_t t[4];
                ldm4(t, sb + TILE_A + rb);
                bf[2 * p][0] = t[0]; bf[2 * p][1] = t[2];
                bf[2 * p + 1][0] = t[1]; bf[2 * p + 1][1] = t[3];
            }
            #pragma unroll
            for (int mf = 0; mf < 2; mf++)
                #pragma unroll
                for (int nf = 0; nf < 4; nf++)
                    mma_f16(acc[mf][nf], ar[mf], bf[nf]);
        }
    }

    const int gid = lane >> 2;
    const int cq = (lane & 3) * 2;
    #pragma unroll
    for (int mf = 0; mf < 2; mf++) {
        const int row0 = m0 + wm * 32 + mf * 16 + gid;
        #pragma unroll
        for (int nf = 0; nf < 4; nf++) {
            const int col = n0 + wn * 32 + nf * 8 + cq;
            const float2 bv = *(const float2*)(bias + col);
            float2 v0, v1;
            v0.x = acc[mf][nf][0] + bv.x;
            v0.y = acc[mf][nf][1] + bv.y;
            v1.x = acc[mf][nf][2] + bv.x;
            v1.y = acc[mf][nf][3] + bv.y;
            if (act) {
                v0.x = (v0.x > 0.f) ? v0.x + 1.f : __expf(v0.x);
                v0.y = (v0.y > 0.f) ? v0.y + 1.f : __expf(v0.y);
                v1.x = (v1.x > 0.f) ? v1.x + 1.f : __expf(v1.x);
                v1.y = (v1.y > 0.f) ? v1.y + 1.f : __expf(v1.y);
            }
            if (fp16out) {
                __half* Ch = (__half*)C;
                *(__half2*)(Ch + (size_t)row0 * DIM + col) =
                    __halves2half2(__float2half_rn(v0.x), __float2half_rn(v0.y));
                *(__half2*)(Ch + (size_t)(row0 + 8) * DIM + col) =
                    __halves2half2(__float2half_rn(v1.x), __float2half_rn(v1.y));
            } else {
                float* Cf = (float*)C;
                *(float2*)(Cf + (size_t)row0 * DIM + col) = v0;
                *(float2*)(Cf + (size_t)(row0 + 8) * DIM + col) = v1;
            }
        }
    }
}

// ---------------------------------------------------------------------------
// fused Q/K/V GEMM: grid.x in [0,24): matrix = x>>3, n-tile = x&7
// ---------------------------------------------------------------------------
__global__ __launch_bounds__(GTHREADS, 1)
void gemm_qkv_kernel(const float* __restrict__ bq,
                     const float* __restrict__ bk,
                     const float* __restrict__ bv)
{
    extern __shared__ __align__(16) char smem[];
    const int nb = blockIdx.x;
    const int mat = nb >> 3;
    const int n0 = (nb & 7) * GBN;
    const int m0 = blockIdx.y * GBM;

    const float* bias;
    __half* C;
    int act;
    if (mat == 0)      { bias = bq; C = g_Q; act = 1; }
    else if (mat == 1) { bias = bk; C = g_K; act = 1; }
    else               { bias = bv; C = g_V; act = 0; }

    gemm_body(g_xh, g_wh[mat], bias, C, m0, n0, act, 1, smem);
}

__global__ __launch_bounds__(GTHREADS, 1)
void gemm_o_kernel(const float* __restrict__ bias, float* __restrict__ C)
{
    extern __shared__ __align__(16) char smem[];
    gemm_body(g_ah, g_wh[3], bias, C,
              blockIdx.y * GBM, blockIdx.x * GBN, 0, 0, smem);
}

// ===========================================================================
// Tensor-core kv_kernel (unchanged from R13)
// ===========================================================================
#define KV_CH   64
#define KV_NSEG 8
#define KV_SEGROWS (NSEQ / KV_NSEG)          // 512
#define KV_NCH  (KV_SEGROWS / KV_CH)         // 8
#define KV_TILE (KV_CH * 144)                // 9216 bytes

__global__ __launch_bounds__(256)
void kv_kernel()
{
    __shared__ __align__(16) char ksm[2][KV_TILE];
    __shared__ __align__(16) char vsm[2][KV_TILE];
    __shared__ __align__(16) float red[64][66];

    const int bh = blockIdx.x;
    const int seg = blockIdx.y;
    const int b = bh >> 4, h = bh & 15;
    const int tid = threadIdx.x;
    const int lane = tid & 31;
    const int wid = tid >> 5;
    const int dfrag = wid & 3;
    const int nhalf = wid >> 2;

    const size_t base = ((size_t)b * NSEQ + seg * KV_SEGROWS) * DIM + h * HD;
    const uint32_t ksb = smem_u32(&ksm[0][0]);
    const uint32_t vsb = smem_u32(&vsm[0][0]);

    auto load_chunk = [&](int ch, int buf) {
        const size_t cbase = base + (size_t)ch * KV_CH * DIM;
        #pragma unroll
        for (int i = 0; i < 4; i++) {
            const int id = tid + i * 256;
            const int r = (id >> 3) & 63;
            const int c = id & 7;
            const uint32_t dst = ((id < 512) ? ksb : vsb) + buf * KV_TILE
                                 + r * 144 + c * 16;
            const __half* src = ((id < 512) ? g_K : g_V)
                                + cbase + (size_t)r * DIM + c * 8;
            cp16(dst, src);
        }
    };

    float acc[8][4];
    #pragma unroll
    for (int j = 0; j < 8; j++)
        #pragma unroll
        for (int e = 0; e < 4; e++) acc[j][e] = 0.f;
    float ksum = 0.f;

    const int arow = (lane & 7) + ((lane >> 4) << 3);
    const int acolB = ((lane >> 3) & 1) * 16;
    const int brow = lane & 15;
    const int bcolB = (lane >> 4) * 16;

    load_chunk(0, 0);
    asm volatile("cp.async.commit_group;");
    load_chunk(1, 1);
    asm volatile("cp.async.commit_group;");

    for (int ch = 0; ch < KV_NCH; ch++) {
        asm volatile("cp.async.wait_group 1;");
        __syncthreads();
        const int buf = ch & 1;
        const uint32_t kb = ksb + buf * KV_TILE;
        const uint32_t vb = vsb + buf * KV_TILE;

        #pragma unroll
        for (int s2 = 0; s2 < 2; s2++) {
            const int s = nhalf * 2 + s2;
            uint32_t a[4];
            ldm4t(a, kb + (16 * s + arow) * 144 + dfrag * 32 + acolB);
            #pragma unroll
            for (int vc = 0; vc < 4; vc++) {
                uint32_t t[4];
                ldm4t(t, vb + (16 * s + brow) * 144 + vc * 32 + bcolB);
                uint32_t b0[2] = { t[0], t[1] };
                uint32_t b1[2] = { t[2], t[3] };
                mma_f16(acc[2 * vc],     a, b0);
                mma_f16(acc[2 * vc + 1], a, b1);
            }
        }

        if (tid < 64) {
            const char* kp = &ksm[buf][0] + tid * 2;
            #pragma unroll 8
            for (int r = 0; r < KV_CH; r++)
                ksum += __half2float(*(const __half*)(kp + r * 144));
        }
        __syncthreads();
        if (ch + 2 < KV_NCH) load_chunk(ch + 2, buf);
        asm volatile("cp.async.commit_group;");
    }

    const int d0 = dfrag * 16 + (lane >> 2);
    if (nhalf == 0) {
        #pragma unroll
        for (int j = 0; j < 8; j++) {
            const int v0 = j * 8 + (lane & 3) * 2;
            red[d0][v0]     = acc[j][0]; red[d0][v0 + 1]     = acc[j][1];
            red[d0 + 8][v0] = acc[j][2]; red[d0 + 8][v0 + 1] = acc[j][3];
        }
    }
    __syncthreads();
    if (nhalf == 1) {
        float* kvout = g_KV + bh * (HD * HD);
        #pragma unroll
        for (int j = 0; j < 8; j++) {
            const int v0 = j * 8 + (lane & 3) * 2;
            atomicAdd(&kvout[d0 * HD + v0],           acc[j][0] + red[d0][v0]);
            atomicAdd(&kvout[d0 * HD + v0 + 1],       acc[j][1] + red[d0][v0 + 1]);
            atomicAdd(&kvout[(d0 + 8) * HD + v0],     acc[j][2] + red[d0 + 8][v0]);
            atomicAdd(&kvout[(d0 + 8) * HD + v0 + 1], acc[j][3] + red[d0 + 8][v0 + 1]);
        }
    }
    if (tid < 64) atomicAdd(&g_Ksum[bh * HD + tid], ksum);
}

// ===========================================================================
// Tensor-core attn_kernel (unchanged from R14)
// ===========================================================================
#define AT_ROWS 128
#define AT_QS 144
#define AT_KS 160

__global__ __launch_bounds__(256)
void attn_kernel(const float* __restrict__ stdp,
                 __half* __restrict__ outh)
{
    __shared__ __align__(16) char qsm[AT_ROWS * AT_QS];
    __shared__ __align__(16) char kvsm[64 * AT_KS];

    const int bh = blockIdx.y;
    const int b = bh >> 4, h = bh & 15;
    const int n0 = blockIdx.x * AT_ROWS;
    const int tid = threadIdx.x;
    const int lane = tid & 31;
    const int wid = tid >> 5;

    const uint32_t qsb = smem_u32(qsm);
    const uint32_t kvb = smem_u32(kvsm);

    const size_t qbase = ((size_t)b * NSEQ + n0) * DIM + h * HD;
    #pragma unroll
    for (int i = 0; i < 4; i++) {
        const int id = tid + i * 256;
        const int r = id >> 3, c = id & 7;
        cp16(qsb + r * AT_QS + c * 16, g_Q + qbase + (size_t)r * DIM + c * 8);
    }
    asm volatile("cp.async.commit_group;");

    const float* kvsrc = g_KV + bh * (HD * HD);
    #pragma unroll
    for (int i = 0; i < 16; i++) {
        const int idx = tid + i * 256;
        const int d = idx >> 6, v = idx & 63;
        *(__half*)(kvsm + d * AT_KS + v * 2) = __float2half_rn(kvsrc[idx]);
    }
    if (tid < 64) {
        *(__half*)(kvsm + tid * AT_KS + 64 * 2) =
            __float2half_rn(g_Ksum[bh * HD + tid]);
        #pragma unroll
        for (int z = 65; z < 80; z++)
            *(__half*)(kvsm + tid * AT_KS + z * 2) = __ushort_as_half(0);
    }
    asm volatile("cp.async.wait_group 0;");
    __syncthreads();

    float acc[9][4];
    #pragma unroll
    for (int j = 0; j < 9; j++)
        #pragma unroll
        for (int e = 0; e < 4; e++) acc[j][e] = 0.f;

    const int rl = lane & 15;
    const int cb16 = (lane >> 4) << 4;
    const int brow = lane & 15;
    const int bcolB = (lane >> 4) * 16;

    #pragma unroll
    for (int s = 0; s < 4; s++) {
        uint32_t a[4];
        ldm4(a, qsb + (wid * 16 + rl) * AT_QS + s * 32 + cb16);
        #pragma unroll
        for (int vc = 0; vc < 4; vc++) {
            uint32_t t[4];
            ldm4t(t, kvb + (16 * s + brow) * AT_KS + vc * 32 + bcolB);
            uint32_t b0[2] = { t[0], t[1] };
            uint32_t b1[2] = { t[2], t[3] };
            mma_f16(acc[2 * vc],     a, b0);
            mma_f16(acc[2 * vc + 1], a, b1);
        }
        {
            uint32_t t[4];
            ldm4t(t, kvb + (16 * s + brow) * AT_KS + 4 * 32 + bcolB);
            uint32_t b0[2] = { t[0], t[1] };
            mma_f16(acc[8], a, b0);
        }
    }

    const float sig = 1.f / (1.f + expf(-stdp[h]));
    const int srcl = lane & ~3;
    const float den0 = __shfl_sync(0xffffffffu, acc[8][0], srcl);
    const float den1 = __shfl_sync(0xffffffffu, acc[8][2], srcl);
    const float sc0 = sig / (den0 + 1e-6f);
    const float sc1 = sig / (den1 + 1e-6f);

    const int gid = lane >> 2;
    const int cq = (lane & 3) * 2;
    const int row0 = n0 + wid * 16 + gid;
    const size_t obase = ((size_t)b * NSEQ + row0) * DIM + h * HD;
    #pragma unroll
    for (int j = 0; j < 8; j++) {
        const int col = j * 8 + cq;
        *(__half2*)(outh + obase + col) =
            __halves2half2(__float2half_rn(acc[j][0] * sc0),
                           __float2half_rn(acc[j][1] * sc0));
        *(__half2*)(outh + obase + (size_t)8 * DIM + col) =
            __halves2half2(__float2half_rn(acc[j][2] * sc1),
                           __float2half_rn(acc[j][3] * sc1));
    }
}

// ---------------------------------------------------------------------------
extern "C" void kernel_launch(void* const* d_in, const int* in_sizes, int n_in,
                              void* d_out, int out_size)
{
    const float* x    = (const float*)d_in[0];
    const float* Wq   = (const float*)d_in[1];
    const float* bq   = (const float*)d_in[2];
    const float* Wk   = (const float*)d_in[3];
    const float* bk   = (const float*)d_in[4];
    const float* Wv   = (const float*)d_in[5];
    const float* bv   = (const float*)d_in[6];
    const float* Wo   = (const float*)d_in[7];
    const float* bo   = (const float*)d_in[8];
    const float* stdp = (const float*)d_in[9];
    float* out = (float*)d_out;

    __half* ah;
    cudaGetSymbolAddress((void**)&ah, g_ah);

    cudaFuncSetAttribute(gemm_qkv_kernel,
                         cudaFuncAttributeMaxDynamicSharedMemorySize, SMEMG);
    cudaFuncSetAttribute(gemm_o_kernel,
                         cudaFuncAttributeMaxDynamicSharedMemorySize, SMEMG);

    const int extra = out_size - MTOT * DIM;

    conv_kernel<<<CV_XBLK + CV_WBLK + CV_ZBLK, 256>>>(
        x, Wq, Wk, Wv, Wo, stdp, out, extra);                           // 0
    gemm_qkv_kernel<<<dim3(24, MTOT / GBM), GTHREADS, SMEMG>>>(bq, bk, bv); // 1
    kv_kernel<<<dim3(BDIM * HEADS, KV_NSEG), 256>>>();                  // 2
    attn_kernel<<<dim3(NSEQ / AT_ROWS, BDIM * HEADS), 256>>>(stdp, ah); // 3
    gemm_o_kernel<<<dim3(DIM / GBN, MTOT / GBM), GTHREADS, SMEMG>>>(bo, out); // 4
}

// round 16
// speedup vs baseline: 1.5674x; 1.5674x over previous
#include <cuda_runtime.h>
#include <cuda_fp16.h>
#include <math.h>
#include <stdint.h>

// ---------------------------------------------------------------------------
// SpikeAttention (linear attention, ELU+1 feature map)
//   B=4, N=4096, DIM=1024, HEADS=16, HEAD_DIM=64
// Round 16: revert to the R14 configuration (best: 555us) — GBN=256 GEMM
// tiles (operand reuse dominates wave-tail effects; R15's GBN=128 doubled
// A-traffic and regressed 57%). Only change kept from R15: output tail
// folded into conv_kernel (one fewer launch).
// ---------------------------------------------------------------------------

#define BDIM  4
#define NSEQ  4096
#define DIM   1024
#define HEADS 16
#define HD    64
#define MTOT  (BDIM * NSEQ)          // 16384

__device__ float g_KV[BDIM * HEADS * HD * HD];
__device__ float g_Ksum[BDIM * HEADS * HD];

__device__ __align__(16) __half g_Q[(size_t)MTOT * DIM];
__device__ __align__(16) __half g_K[(size_t)MTOT * DIM];
__device__ __align__(16) __half g_V[(size_t)MTOT * DIM];
__device__ __align__(16) __half g_xh[(size_t)MTOT * DIM];
__device__ __align__(16) __half g_ah[(size_t)MTOT * DIM];
__device__ __align__(16) __half g_wh[4][DIM * DIM];

// ---------------------------------------------------------------------------
// fused conversion kernel: x->fp16, W*->fp16, zero KV/Ksum, out tail. 1 launch
// ---------------------------------------------------------------------------
#define CV_XBLK (MTOT * DIM / 4 / 256)       // 16384
#define CV_WBLK 4096
#define CV_ZBLK ((BDIM * HEADS * HD * HD + 255) / 256 + 1)  // 1025
__global__ __launch_bounds__(256)
void conv_kernel(const float* __restrict__ x,
                 const float* __restrict__ Wq, const float* __restrict__ Wk,
                 const float* __restrict__ Wv, const float* __restrict__ Wo,
                 const float* __restrict__ stdp,
                 float* __restrict__ out, int extra)
{
    const int bid = blockIdx.x;
    if (bid < CV_XBLK) {
        const int i = bid * 256 + threadIdx.x;
        float4 f = ((const float4*)x)[i];
        ((__half2*)g_xh)[2 * i + 0] = __halves2half2(__float2half_rn(f.x),
                                                     __float2half_rn(f.y));
        ((__half2*)g_xh)[2 * i + 1] = __halves2half2(__float2half_rn(f.z),
                                                     __float2half_rn(f.w));
    } else if (bid < CV_XBLK + CV_WBLK) {
        const int wb = bid - CV_XBLK;
        const int mat = wb >> 10;
        const int i = (wb & 1023) * 256 + threadIdx.x;
        const float* src = (mat == 0) ? Wq : (mat == 1) ? Wk
                         : (mat == 2) ? Wv : Wo;
        float4 f = ((const float4*)src)[i];
        ((__half2*)g_wh[mat])[2 * i + 0] = __halves2half2(__float2half_rn(f.x),
                                                          __float2half_rn(f.y));
        ((__half2*)g_wh[mat])[2 * i + 1] = __halves2half2(__float2half_rn(f.z),
                                                          __float2half_rn(f.w));
    } else {
        const int i = (bid - CV_XBLK - CV_WBLK) * 256 + threadIdx.x;
        if (i < BDIM * HEADS * HD * HD) g_KV[i] = 0.f;
        if (i < BDIM * HEADS * HD)      g_Ksum[i] = 0.f;
        if (i < extra)
            out[(size_t)MTOT * DIM + i] = (i < HEADS) ? stdp[i] : 0.f;
    }
}

// ===========================================================================
// Shared PTX helpers
// ===========================================================================
__device__ __forceinline__ uint32_t smem_u32(const void* p) {
    uint32_t a;
    asm("{ .reg .u64 t; cvta.to.shared.u64 t, %1; cvt.u32.u64 %0, t; }"
        : "=r"(a) : "l"(p));
    return a;
}
__device__ __forceinline__ void cp16(uint32_t dst, const void* src) {
    asm volatile("cp.async.cg.shared.global [%0], [%1], 16;"
                 :: "r"(dst), "l"(src));
}
__device__ __forceinline__ void ldm4(uint32_t* r, uint32_t addr) {
    asm volatile("ldmatrix.sync.aligned.m8n8.x4.shared.b16 {%0,%1,%2,%3}, [%4];"
                 : "=r"(r[0]), "=r"(r[1]), "=r"(r[2]), "=r"(r[3]) : "r"(addr));
}
__device__ __forceinline__ void ldm4t(uint32_t* r, uint32_t addr) {
    asm volatile("ldmatrix.sync.aligned.m8n8.x4.trans.shared.b16 {%0,%1,%2,%3}, [%4];"
                 : "=r"(r[0]), "=r"(r[1]), "=r"(r[2]), "=r"(r[3]) : "r"(addr));
}
__device__ __forceinline__ void mma_f16(float* c, const uint32_t* a,
                                        const uint32_t* b) {
    asm volatile(
        "mma.sync.aligned.m16n8k16.row.col.f32.f16.f16.f32 "
        "{%0,%1,%2,%3}, {%4,%5,%6,%7}, {%8,%9}, {%0,%1,%2,%3};"
        : "+f"(c[0]), "+f"(c[1]), "+f"(c[2]), "+f"(c[3])
        : "r"(a[0]), "r"(a[1]), "r"(a[2]), "r"(a[3]), "r"(b[0]), "r"(b[1]));
}

// ===========================================================================
// GEMM core: 128x256 CTA tile, GBK=64, 4-stage cp.async, 512 threads,
// 16 warps (4M x 4N), each warp owns 32x64. (R14 configuration.)
// ===========================================================================
#define GBM 128
#define GBN 256
#define GBK 64
#define NCHUNK (DIM / GBK)           // 16
#define RS 144
#define TILE_A (128 * RS)            // 18432
#define TILE_W (256 * RS)            // 36864
#define STAGE_B (TILE_A + TILE_W)    // 55296
#define GSTAGES 4
#define SMEMG (GSTAGES * STAGE_B)    // 221184
#define GTHREADS 512

__device__ __forceinline__
void gemm_body(const __half* __restrict__ A,
               const __half* __restrict__ W,
               const float* __restrict__ bias,
               void* __restrict__ C,
               int m0, int n0, int act, int fp16out, char* smem)
{
    const uint32_t sbase = smem_u32(smem);
    const int tid = threadIdx.x;
    const int lane = tid & 31;
    const int wid = tid >> 5;
    const int wm = wid & 3;
    const int wn = wid >> 2;

    auto load_stage = [&](int ck, int slot) {
        const uint32_t sb = sbase + slot * STAGE_B;
        const int kofs = ck * GBK;
        #pragma unroll
        for (int i = 0; i < 6; i++) {
            const int id = tid + i * GTHREADS;
            uint32_t dst;
            const __half* src;
            if (id < 1024) {
                const int r = id >> 3, c = id & 7;
                dst = sb + r * RS + c * 16;
                src = A + (size_t)(m0 + r) * DIM + kofs + c * 8;
            } else {
                const int id2 = id - 1024;
                const int r = id2 >> 3, c = id2 & 7;
                dst = sb + TILE_A + r * RS + c * 16;
                src = W + (size_t)(n0 + r) * DIM + kofs + c * 8;
            }
            cp16(dst, src);
        }
    };

    load_stage(0, 0);
    asm volatile("cp.async.commit_group;");
    load_stage(1, 1);
    asm volatile("cp.async.commit_group;");
    load_stage(2, 2);
    asm volatile("cp.async.commit_group;");

    float acc[2][8][4];
    #pragma unroll
    for (int mf = 0; mf < 2; mf++)
        #pragma unroll
        for (int nf = 0; nf < 8; nf++)
            #pragma unroll
            for (int e = 0; e < 4; e++) acc[mf][nf][e] = 0.f;

    const int rl = lane & 15;
    const int cb16 = (lane >> 4) << 4;

    for (int ck = 0; ck < NCHUNK; ck++) {
        asm volatile("cp.async.wait_group 2;");
        __syncthreads();
        if (ck + 3 < NCHUNK) load_stage(ck + 3, (ck + 3) & (GSTAGES - 1));
        asm volatile("cp.async.commit_group;");

        const uint32_t sb = sbase + (ck & (GSTAGES - 1)) * STAGE_B;
        #pragma unroll
        for (int k16 = 0; k16 < 4; k16++) {
            const int cb = k16 * 32 + cb16;
            uint32_t ar[2][4], bf[8][2];
            #pragma unroll
            for (int mf = 0; mf < 2; mf++) {
                const uint32_t ra = (wm * 32 + mf * 16 + rl) * RS + cb;
                ldm4(ar[mf], sb + ra);
            }
            #pragma unroll
            for (int p = 0; p < 4; p++) {
                const uint32_t rb = (wn * 64 + p * 16 + rl) * RS + cb;
                uint32_t t[4];
                ldm4(t, sb + TILE_A + rb);
                bf[2 * p][0] = t[0]; bf[2 * p][1] = t[2];
                bf[2 * p + 1][0] = t[1]; bf[2 * p + 1][1] = t[3];
            }
            #pragma unroll
            for (int mf = 0; mf < 2; mf++)
                #pragma unroll
                for (int nf = 0; nf < 8; nf++)
                    mma_f16(acc[mf][nf], ar[mf], bf[nf]);
        }
    }

    const int gid = lane >> 2;
    const int cq = (lane & 3) * 2;
    #pragma unroll
    for (int mf = 0; mf < 2; mf++) {
        const int row0 = m0 + wm * 32 + mf * 16 + gid;
        #pragma unroll
        for (int nf = 0; nf < 8; nf++) {
            const int col = n0 + wn * 64 + nf * 8 + cq;
            const float2 bv = *(const float2*)(bias + col);
            float2 v0, v1;
            v0.x = acc[mf][nf][0] + bv.x;
            v0.y = acc[mf][nf][1] + bv.y;
            v1.x = acc[mf][nf][2] + bv.x;
            v1.y = acc[mf][nf][3] + bv.y;
            if (act) {
                v0.x = (v0.x > 0.f) ? v0.x + 1.f : __expf(v0.x);
                v0.y = (v0.y > 0.f) ? v0.y + 1.f : __expf(v0.y);
                v1.x = (v1.x > 0.f) ? v1.x + 1.f : __expf(v1.x);
                v1.y = (v1.y > 0.f) ? v1.y + 1.f : __expf(v1.y);
            }
            if (fp16out) {
                __half* Ch = (__half*)C;
                *(__half2*)(Ch + (size_t)row0 * DIM + col) =
                    __halves2half2(__float2half_rn(v0.x), __float2half_rn(v0.y));
                *(__half2*)(Ch + (size_t)(row0 + 8) * DIM + col) =
                    __halves2half2(__float2half_rn(v1.x), __float2half_rn(v1.y));
            } else {
                float* Cf = (float*)C;
                *(float2*)(Cf + (size_t)row0 * DIM + col) = v0;
                *(float2*)(Cf + (size_t)(row0 + 8) * DIM + col) = v1;
            }
        }
    }
}

// ---------------------------------------------------------------------------
// fused Q/K/V GEMM: grid.x in [0,12): matrix = x>>2, n-tile = x&3
// ---------------------------------------------------------------------------
__global__ __launch_bounds__(GTHREADS, 1)
void gemm_qkv_kernel(const float* __restrict__ bq,
                     const float* __restrict__ bk,
                     const float* __restrict__ bv)
{
    extern __shared__ __align__(16) char smem[];
    const int nb = blockIdx.x;
    const int mat = nb >> 2;
    const int n0 = (nb & 3) * GBN;
    const int m0 = blockIdx.y * GBM;

    const float* bias;
    __half* C;
    int act;
    if (mat == 0)      { bias = bq; C = g_Q; act = 1; }
    else if (mat == 1) { bias = bk; C = g_K; act = 1; }
    else               { bias = bv; C = g_V; act = 0; }

    gemm_body(g_xh, g_wh[mat], bias, C, m0, n0, act, 1, smem);
}

__global__ __launch_bounds__(GTHREADS, 1)
void gemm_o_kernel(const float* __restrict__ bias, float* __restrict__ C)
{
    extern __shared__ __align__(16) char smem[];
    gemm_body(g_ah, g_wh[3], bias, C,
              blockIdx.y * GBM, blockIdx.x * GBN, 0, 0, smem);
}

// ===========================================================================
// Tensor-core kv_kernel (R13)
// ===========================================================================
#define KV_CH   64
#define KV_NSEG 8
#define KV_SEGROWS (NSEQ / KV_NSEG)          // 512
#define KV_NCH  (KV_SEGROWS / KV_CH)         // 8
#define KV_TILE (KV_CH * 144)                // 9216 bytes

__global__ __launch_bounds__(256)
void kv_kernel()
{
    __shared__ __align__(16) char ksm[2][KV_TILE];
    __shared__ __align__(16) char vsm[2][KV_TILE];
    __shared__ __align__(16) float red[64][66];

    const int bh = blockIdx.x;
    const int seg = blockIdx.y;
    const int b = bh >> 4, h = bh & 15;
    const int tid = threadIdx.x;
    const int lane = tid & 31;
    const int wid = tid >> 5;
    const int dfrag = wid & 3;
    const int nhalf = wid >> 2;

    const size_t base = ((size_t)b * NSEQ + seg * KV_SEGROWS) * DIM + h * HD;
    const uint32_t ksb = smem_u32(&ksm[0][0]);
    const uint32_t vsb = smem_u32(&vsm[0][0]);

    auto load_chunk = [&](int ch, int buf) {
        const size_t cbase = base + (size_t)ch * KV_CH * DIM;
        #pragma unroll
        for (int i = 0; i < 4; i++) {
            const int id = tid + i * 256;
            const int r = (id >> 3) & 63;
            const int c = id & 7;
            const uint32_t dst = ((id < 512) ? ksb : vsb) + buf * KV_TILE
                                 + r * 144 + c * 16;
            const __half* src = ((id < 512) ? g_K : g_V)
                                + cbase + (size_t)r * DIM + c * 8;
            cp16(dst, src);
        }
    };

    float acc[8][4];
    #pragma unroll
    for (int j = 0; j < 8; j++)
        #pragma unroll
        for (int e = 0; e < 4; e++) acc[j][e] = 0.f;
    float ksum = 0.f;

    const int arow = (lane & 7) + ((lane >> 4) << 3);
    const int acolB = ((lane >> 3) & 1) * 16;
    const int brow = lane & 15;
    const int bcolB = (lane >> 4) * 16;

    load_chunk(0, 0);
    asm volatile("cp.async.commit_group;");
    load_chunk(1, 1);
    asm volatile("cp.async.commit_group;");

    for (int ch = 0; ch < KV_NCH; ch++) {
        asm volatile("cp.async.wait_group 1;");
        __syncthreads();
        const int buf = ch & 1;
        const uint32_t kb = ksb + buf * KV_TILE;
        const uint32_t vb = vsb + buf * KV_TILE;

        #pragma unroll
        for (int s2 = 0; s2 < 2; s2++) {
            const int s = nhalf * 2 + s2;
            uint32_t a[4];
            ldm4t(a, kb + (16 * s + arow) * 144 + dfrag * 32 + acolB);
            #pragma unroll
            for (int vc = 0; vc < 4; vc++) {
                uint32_t t[4];
                ldm4t(t, vb + (16 * s + brow) * 144 + vc * 32 + bcolB);
                uint32_t b0[2] = { t[0], t[1] };
                uint32_t b1[2] = { t[2], t[3] };
                mma_f16(acc[2 * vc],     a, b0);
                mma_f16(acc[2 * vc + 1], a, b1);
            }
        }

        if (tid < 64) {
            const char* kp = &ksm[buf][0] + tid * 2;
            #pragma unroll 8
            for (int r = 0; r < KV_CH; r++)
                ksum += __half2float(*(const __half*)(kp + r * 144));
        }
        __syncthreads();
        if (ch + 2 < KV_NCH) load_chunk(ch + 2, buf);
        asm volatile("cp.async.commit_group;");
    }

    const int d0 = dfrag * 16 + (lane >> 2);
    if (nhalf == 0) {
        #pragma unroll
        for (int j = 0; j < 8; j++) {
            const int v0 = j * 8 + (lane & 3) * 2;
            red[d0][v0]     = acc[j][0]; red[d0][v0 + 1]     = acc[j][1];
            red[d0 + 8][v0] = acc[j][2]; red[d0 + 8][v0 + 1] = acc[j][3];
        }
    }
    __syncthreads();
    if (nhalf == 1) {
        float* kvout = g_KV + bh * (HD * HD);
        #pragma unroll
        for (int j = 0; j < 8; j++) {
            const int v0 = j * 8 + (lane & 3) * 2;
            atomicAdd(&kvout[d0 * HD + v0],           acc[j][0] + red[d0][v0]);
            atomicAdd(&kvout[d0 * HD + v0 + 1],       acc[j][1] + red[d0][v0 + 1]);
            atomicAdd(&kvout[(d0 + 8) * HD + v0],     acc[j][2] + red[d0 + 8][v0]);
            atomicAdd(&kvout[(d0 + 8) * HD + v0 + 1], acc[j][3] + red[d0 + 8][v0 + 1]);
        }
    }
    if (tid < 64) atomicAdd(&g_Ksum[bh * HD + tid], ksum);
}

// ===========================================================================
// Tensor-core attn_kernel (R14)
// ===========================================================================
#define AT_ROWS 128
#define AT_QS 144
#define AT_KS 160

__global__ __launch_bounds__(256)
void attn_kernel(const float* __restrict__ stdp,
                 __half* __restrict__ outh)
{
    __shared__ __align__(16) char qsm[AT_ROWS * AT_QS];
    __shared__ __align__(16) char kvsm[64 * AT_KS];

    const int bh = blockIdx.y;
    const int b = bh >> 4, h = bh & 15;
    const int n0 = blockIdx.x * AT_ROWS;
    const int tid = threadIdx.x;
    const int lane = tid & 31;
    const int wid = tid >> 5;

    const uint32_t qsb = smem_u32(qsm);
    const uint32_t kvb = smem_u32(kvsm);

    const size_t qbase = ((size_t)b * NSEQ + n0) * DIM + h * HD;
    #pragma unroll
    for (int i = 0; i < 4; i++) {
        const int id = tid + i * 256;
        const int r = id >> 3, c = id & 7;
        cp16(qsb + r * AT_QS + c * 16, g_Q + qbase + (size_t)r * DIM + c * 8);
    }
    asm volatile("cp.async.commit_group;");

    const float* kvsrc = g_KV + bh * (HD * HD);
    #pragma unroll
    for (int i = 0; i < 16; i++) {
        const int idx = tid + i * 256;
        const int d = idx >> 6, v = idx & 63;
        *(__half*)(kvsm + d * AT_KS + v * 2) = __float2half_rn(kvsrc[idx]);
    }
    if (tid < 64) {
        *(__half*)(kvsm + tid * AT_KS + 64 * 2) =
            __float2half_rn(g_Ksum[bh * HD + tid]);
        #pragma unroll
        for (int z = 65; z < 80; z++)
            *(__half*)(kvsm + tid * AT_KS + z * 2) = __ushort_as_half(0);
    }
    asm volatile("cp.async.wait_group 0;");
    __syncthreads();

    float acc[9][4];
    #pragma unroll
    for (int j = 0; j < 9; j++)
        #pragma unroll
        for (int e = 0; e < 4; e++) acc[j][e] = 0.f;

    const int rl = lane & 15;
    const int cb16 = (lane >> 4) << 4;
    const int brow = lane & 15;
    const int bcolB = (lane >> 4) * 16;

    #pragma unroll
    for (int s = 0; s < 4; s++) {
        uint32_t a[4];
        ldm4(a, qsb + (wid * 16 + rl) * AT_QS + s * 32 + cb16);
        #pragma unroll
        for (int vc = 0; vc < 4; vc++) {
            uint32_t t[4];
            ldm4t(t, kvb + (16 * s + brow) * AT_KS + vc * 32 + bcolB);
            uint32_t b0[2] = { t[0], t[1] };
            uint32_t b1[2] = { t[2], t[3] };
            mma_f16(acc[2 * vc],     a, b0);
            mma_f16(acc[2 * vc + 1], a, b1);
        }
        {
            uint32_t t[4];
            ldm4t(t, kvb + (16 * s + brow) * AT_KS + 4 * 32 + bcolB);
            uint32_t b0[2] = { t[0], t[1] };
            mma_f16(acc[8], a, b0);
        }
    }

    const float sig = 1.f / (1.f + expf(-stdp[h]));
    const int srcl = lane & ~3;
    const float den0 = __shfl_sync(0xffffffffu, acc[8][0], srcl);
    const float den1 = __shfl_sync(0xffffffffu, acc[8][2], srcl);
    const float sc0 = sig / (den0 + 1e-6f);
    const float sc1 = sig / (den1 + 1e-6f);

    const int gid = lane >> 2;
    const int cq = (lane & 3) * 2;
    const int row0 = n0 + wid * 16 + gid;
    const size_t obase = ((size_t)b * NSEQ + row0) * DIM + h * HD;
    #pragma unroll
    for (int j = 0; j < 8; j++) {
        const int col = j * 8 + cq;
        *(__half2*)(outh + obase + col) =
            __halves2half2(__float2half_rn(acc[j][0] * sc0),
                           __float2half_rn(acc[j][1] * sc0));
        *(__half2*)(outh + obase + (size_t)8 * DIM + col) =
            __halves2half2(__float2half_rn(acc[j][2] * sc1),
                           __float2half_rn(acc[j][3] * sc1));
    }
}

// ---------------------------------------------------------------------------
extern "C" void kernel_launch(void* const* d_in, const int* in_sizes, int n_in,
                              void* d_out, int out_size)
{
    const float* x    = (const float*)d_in[0];
    const float* Wq   = (const float*)d_in[1];
    const float* bq   = (const float*)d_in[2];
    const float* Wk   = (const float*)d_in[3];
    const float* bk   = (const float*)d_in[4];
    const float* Wv   = (const float*)d_in[5];
    const float* bv   = (const float*)d_in[6];
    const float* Wo   = (const float*)d_in[7];
    const float* bo   = (const float*)d_in[8];
    const float* stdp = (const float*)d_in[9];
    float* out = (float*)d_out;

    __half* ah;
    cudaGetSymbolAddress((void**)&ah, g_ah);

    cudaFuncSetAttribute(gemm_qkv_kernel,
                         cudaFuncAttributeMaxDynamicSharedMemorySize, SMEMG);
    cudaFuncSetAttribute(gemm_o_kernel,
                         cudaFuncAttributeMaxDynamicSharedMemorySize, SMEMG);

    const int extra = out_size - MTOT * DIM;

    conv_kernel<<<CV_XBLK + CV_WBLK + CV_ZBLK, 256>>>(
        x, Wq, Wk, Wv, Wo, stdp, out, extra);                           // 0
    gemm_qkv_kernel<<<dim3(12, MTOT / GBM), GTHREADS, SMEMG>>>(bq, bk, bv); // 1
    kv_kernel<<<dim3(BDIM * HEADS, KV_NSEG), 256>>>();                  // 2
    attn_kernel<<<dim3(NSEQ / AT_ROWS, BDIM * HEADS), 256>>>(stdp, ah); // 3
    gemm_o_kernel<<<dim3(DIM / GBN, MTOT / GBM), GTHREADS, SMEMG>>>(bo, out); // 4
}